// round 2
// baseline (speedup 1.0000x reference)
#include <cuda_runtime.h>

#define BATCH 32
#define NNODE 128
#define NIN_F 64
#define EDGES (NNODE * (NNODE - 1))   // 16256
#define MHID 256
#define MOUT 64
#define NHID 256
#define NOUT 64

// ---------------- static device scratch (no allocations allowed) ----------------
__device__ float g_W1t[128 * 256];        // W1t[i*256+o] = W1[o,i]   (i<64 sender, i>=64 recv)
__device__ float g_W2t[256 * 64];         // W2t[k*64+m]  = W2[m,k]
__device__ float g_O1t[64 * 256];         // O1t[m*256+j] = O1[j,m]
__device__ float g_O2t[256 * 256];        // O2t[m*256+j] = O2[j,m]
__device__ float g_O3t[256 * 64];         // O3t[j*64+m]  = O3[m,j]
__device__ float g_H1s[BATCH * NNODE * 256];
__device__ float g_H1r[BATCH * NNODE * 256];

// ---------------- packed f32x2 helpers ----------------
__device__ __forceinline__ unsigned long long dup2(float v) {
    unsigned long long r;
    unsigned u = __float_as_uint(v);
    asm("mov.b64 %0, {%1, %2};" : "=l"(r) : "r"(u), "r"(u));
    return r;
}
__device__ __forceinline__ void fma2(unsigned long long& d, unsigned long long a,
                                     unsigned long long b) {
    asm("fma.rn.f32x2 %0, %1, %2, %0;" : "+l"(d) : "l"(a), "l"(b));
}

// ---------------- kernel A: weight transposes ----------------
__global__ void transpose_kernel(const float* __restrict__ W1, const float* __restrict__ W2,
                                 const float* __restrict__ O1, const float* __restrict__ O2,
                                 const float* __restrict__ O3) {
    const int total = 32768 + 16384 + 16384 + 65536 + 16384;
    for (int t = blockIdx.x * blockDim.x + threadIdx.x; t < total;
         t += gridDim.x * blockDim.x) {
        int x = t;
        if (x < 32768) {                      // W1 [256][128] -> [128][256]
            int i = x / 256, o = x % 256;
            g_W1t[x] = W1[o * 128 + i];
        } else if ((x -= 32768) < 16384) {    // W2 [64][256] -> [256][64]
            int k = x / 64, m = x % 64;
            g_W2t[x] = W2[m * 256 + k];
        } else if ((x -= 16384) < 16384) {    // O1 [256][64] -> [64][256]
            int m = x / 256, j = x % 256;
            g_O1t[x] = O1[j * 64 + m];
        } else if ((x -= 16384) < 65536) {    // O2 [256][256] -> [256][256] (T)
            int m = x / 256, j = x % 256;
            g_O2t[x] = O2[j * 256 + m];
        } else {                              // O3 [64][256] -> [256][64]
            x -= 65536;
            int j = x / 64, m = x % 64;
            g_O3t[x] = O3[m * 256 + j];
        }
    }
}

// ---------------- kernel B: per-node layer-1 halves ----------------
// H1s[row,o] = sum_i x[i] * W1[o,i]         (sender half)
// H1r[row,o] = sum_i x[i] * W1[o,64+i] + b1 (receiver half + bias)
__global__ void __launch_bounds__(256) h1_kernel(const float* __restrict__ inp,
                                                 const float* __restrict__ b1) {
    const int row = blockIdx.x;  // b*128 + n
    const int tid = threadIdx.x;
    __shared__ float xs[64];
    if (tid < 64) xs[tid] = inp[row * 64 + tid];
    __syncthreads();
    float hs = 0.f, hr = b1[tid];
#pragma unroll
    for (int i = 0; i < 64; ++i) {
        float x = xs[i];
        hs = fmaf(x, __ldg(&g_W1t[i * 256 + tid]), hs);
        hr = fmaf(x, __ldg(&g_W1t[(64 + i) * 256 + tid]), hr);
    }
    g_H1s[row * 256 + tid] = hs;
    g_H1r[row * 256 + tid] = hr;
}

// ---------------- kernel C: fused edge GEMM + aggregation + node MLP ----------------
// One CTA per (b, r). Edges e=0..126 of this receiver group; sender = e + (e>=r).
// GEMM tile: 128 edge slots (last padded) x 64 outputs, K=256 in chunks of 64.
// Thread (ti = lane, tj = warp): edges 4*ti..4*ti+3, outputs tj*8..tj*8+7.
__global__ void __launch_bounds__(256) main_kernel(const float* __restrict__ rt,
                                                   const float* __restrict__ b2,
                                                   const float* __restrict__ o1b,
                                                   const float* __restrict__ o2b,
                                                   const float* __restrict__ o3b,
                                                   float* __restrict__ out) {
    const int r = blockIdx.x;
    const int b = blockIdx.y;
    const int tid = threadIdx.x;
    const int ti = tid & 31;
    const int tj = tid >> 5;

    __shared__ float h1t[64][132];  // transposed K-chunk of h1: h1t[k][edge]
    __shared__ float h1r_s[256];
    __shared__ float rts_s[128];
    __shared__ float agg_s[64];
    __shared__ float hb0[256];
    __shared__ float hb1[256];

    const int node_base = (b * NNODE + r) * 256;
    h1r_s[tid] = g_H1r[node_base + tid];
    if (tid < 128) {
        float v = 0.f;
        if (tid < 127) {
            const float* p = rt + ((size_t)b * EDGES + (size_t)r * 127 + tid) * 2;
            v = p[0] + p[1];
        }
        rts_s[tid] = v;
    }
    __syncthreads();

    unsigned long long acc[4][4];
#pragma unroll
    for (int j = 0; j < 4; ++j)
#pragma unroll
        for (int p = 0; p < 4; ++p) acc[j][p] = 0ull;

    const int bbase = b * NNODE * 256;
    for (int kb = 0; kb < 256; kb += 64) {
        // ---- stage h1 chunk (transposed into smem) ----
#pragma unroll 4
        for (int it = 0; it < 32; ++it) {
            int idx = it * 256 + tid;
            int e = idx >> 6, kk = idx & 63;
            float v = 0.f;
            if (e < 127) {
                int sidx = e + (e >= r);
                v = fmaxf(g_H1s[bbase + sidx * 256 + kb + kk] + h1r_s[kb + kk], 0.f);
            }
            h1t[kk][e] = v;
        }
        __syncthreads();

        const float* wbase = g_W2t + kb * 64 + tj * 8;
#pragma unroll 16
        for (int kk = 0; kk < 64; ++kk) {
            float4 a4 = *(const float4*)&h1t[kk][ti * 4];
            ulonglong2 wA = __ldg((const ulonglong2*)(wbase + (size_t)kk * 64));
            ulonglong2 wB = __ldg((const ulonglong2*)(wbase + (size_t)kk * 64 + 4));
#pragma unroll
            for (int j = 0; j < 4; ++j) {
                unsigned long long ad = dup2((&a4.x)[j]);
                fma2(acc[j][0], ad, wA.x);
                fma2(acc[j][1], ad, wA.y);
                fma2(acc[j][2], ad, wB.x);
                fma2(acc[j][3], ad, wB.y);
            }
        }
        __syncthreads();
    }

    // ---- bias + relu + rt-weight + reduce over edges ----
    float b2v[8];
#pragma unroll
    for (int q = 0; q < 8; ++q) b2v[q] = __ldg(&b2[tj * 8 + q]);
    float psum[8];
#pragma unroll
    for (int q = 0; q < 8; ++q) psum[q] = 0.f;
#pragma unroll
    for (int j = 0; j < 4; ++j) {
        float rv = rts_s[ti * 4 + j];
#pragma unroll
        for (int p = 0; p < 4; ++p) {
            float lo = __uint_as_float((unsigned)(acc[j][p] & 0xffffffffull));
            float hi = __uint_as_float((unsigned)(acc[j][p] >> 32));
            psum[2 * p] += fmaxf(lo + b2v[2 * p], 0.f) * rv;
            psum[2 * p + 1] += fmaxf(hi + b2v[2 * p + 1], 0.f) * rv;
        }
    }
#pragma unroll
    for (int off = 16; off > 0; off >>= 1)
#pragma unroll
        for (int q = 0; q < 8; ++q)
            psum[q] += __shfl_xor_sync(0xffffffffu, psum[q], off);
    if (ti == 0) {
#pragma unroll
        for (int q = 0; q < 8; ++q) agg_s[tj * 8 + q] = psum[q];
    }
    __syncthreads();

    // ---- node MLP: 64 -> 256 -> 256 -> 64 ----
    {
        float a = o1b[tid];
#pragma unroll 8
        for (int m = 0; m < 64; ++m)
            a = fmaf(agg_s[m], __ldg(&g_O1t[m * 256 + tid]), a);
        hb0[tid] = fmaxf(a, 0.f);
    }
    __syncthreads();
    {
        float a = o2b[tid];
#pragma unroll 8
        for (int m = 0; m < 256; ++m)
            a = fmaf(hb0[m], __ldg(&g_O2t[m * 256 + tid]), a);
        hb1[tid] = fmaxf(a, 0.f);
    }
    __syncthreads();
    if (tid < 64) {
        float a = o3b[tid];
#pragma unroll 8
        for (int j = 0; j < 256; ++j)
            a = fmaf(hb1[j], __ldg(&g_O3t[j * 64 + tid]), a);
        out[(b * NNODE + r) * 64 + tid] = a;
    }
}

// ---------------- launch ----------------
extern "C" void kernel_launch(void* const* d_in, const int* in_sizes, int n_in,
                              void* d_out, int out_size) {
    const float* inputs = (const float*)d_in[0];
    // d_in[1] = rel_rec, d_in[2] = rel_send: structure known analytically, unused
    const float* rel_types = (const float*)d_in[3];
    const float* W1 = (const float*)d_in[4];
    const float* b1 = (const float*)d_in[5];
    const float* W2 = (const float*)d_in[6];
    const float* b2 = (const float*)d_in[7];
    const float* O1 = (const float*)d_in[8];
    const float* o1b = (const float*)d_in[9];
    const float* O2 = (const float*)d_in[10];
    const float* o2b = (const float*)d_in[11];
    const float* O3 = (const float*)d_in[12];
    const float* o3b = (const float*)d_in[13];
    float* out = (float*)d_out;

    transpose_kernel<<<144, 256>>>(W1, W2, O1, O2, O3);
    h1_kernel<<<BATCH * NNODE, 256>>>(inputs, b1);
    main_kernel<<<dim3(NNODE, BATCH), 256>>>(rel_types, b2, o1b, o2b, o3b, out);
}

// round 5
// speedup vs baseline: 3.6430x; 3.6430x over previous
#include <cuda_runtime.h>
#include <cuda_fp16.h>
#include <cstdint>

#define BATCH 32
#define NNODE 128
#define EDGES (NNODE * (NNODE - 1))

typedef unsigned long long ull;
typedef uint32_t u32;

// ---------------- static device scratch ----------------
__device__ float g_W1t[128 * 256];     // W1t[i*256+o] = W1[o,i]
__device__ float g_O1t[64 * 256];
__device__ float g_O2t[256 * 256];
__device__ float g_O3t[256 * 64];
__device__ uint4 g_Bf[16 * 8 * 32];    // mma B-fragments: [kstep][ntile][lane] = {hi0,hi1,lo0,lo1}
__device__ u32 g_H1s16[BATCH * NNODE * 128];  // fp16x2 sender-half
__device__ u32 g_H1r16[BATCH * NNODE * 128];  // fp16x2 recv-half (+b1)
__device__ float g_AGG[BATCH * NNODE * 64];

// ---------------- helpers ----------------
__device__ __forceinline__ u32 smem_u32(const void* p) {
    u32 a;
    asm("{ .reg .u64 t; cvta.to.shared.u64 t, %1; cvt.u32.u64 %0, t; }" : "=r"(a) : "l"(p));
    return a;
}
__device__ __forceinline__ ull dup2(float v) {
    ull r; unsigned u = __float_as_uint(v);
    asm("mov.b64 %0, {%1, %2};" : "=l"(r) : "r"(u), "r"(u));
    return r;
}
__device__ __forceinline__ void fma2(ull& d, ull a, ull b) {
    asm("fma.rn.f32x2 %0, %1, %2, %0;" : "+l"(d) : "l"(a), "l"(b));
}
__device__ __forceinline__ float2 unpk(ull v) {
    float2 f; asm("mov.b64 {%0, %1}, %2;" : "=f"(f.x), "=f"(f.y) : "l"(v));
    return f;
}
// pack two f32 -> f16x2 (lo_val in low half)
__device__ __forceinline__ u32 pk_h2(float hi_val, float lo_val) {
    u32 d; asm("cvt.rn.f16x2.f32 %0, %1, %2;" : "=r"(d) : "f"(hi_val), "f"(lo_val));
    return d;
}
// relu(hs + hr) in packed fp16x2, single instruction
__device__ __forceinline__ u32 frelu2(u32 hs, u32 hr) {
    u32 d;
    asm("fma.rn.relu.f16x2 %0, %1, %2, %3;" : "=r"(d) : "r"(hs), "r"(0x3C003C00u), "r"(hr));
    return d;
}
__device__ __forceinline__ void ldmatrix_x4(u32& a0, u32& a1, u32& a2, u32& a3, u32 addr) {
    asm volatile("ldmatrix.sync.aligned.m8n8.x4.shared.b16 {%0,%1,%2,%3}, [%4];"
                 : "=r"(a0), "=r"(a1), "=r"(a2), "=r"(a3) : "r"(addr));
}
__device__ __forceinline__ void hmma(float* c, u32 a0, u32 a1, u32 a2, u32 a3, u32 b0, u32 b1) {
    asm volatile(
        "mma.sync.aligned.m16n8k16.row.col.f32.f16.f16.f32 "
        "{%0,%1,%2,%3}, {%4,%5,%6,%7}, {%8,%9}, {%0,%1,%2,%3};"
        : "+f"(c[0]), "+f"(c[1]), "+f"(c[2]), "+f"(c[3])
        : "r"(a0), "r"(a1), "r"(a2), "r"(a3), "r"(b0), "r"(b1));
}

// ---------------- prep: transposes + mma B-fragments of W2 (fp16 hi+lo) ----------------
__global__ void prep_kernel(const float* __restrict__ W1, const float* __restrict__ W2,
                            const float* __restrict__ O1, const float* __restrict__ O2,
                            const float* __restrict__ O3) {
    const int total = 32768 + 16384 + 65536 + 16384 + 4096;
    for (int t0 = blockIdx.x * blockDim.x + threadIdx.x; t0 < total;
         t0 += gridDim.x * blockDim.x) {
        int x = t0;
        if (x < 32768) {                       // W1t[i*256+o] = W1[o*128+i]
            int i = x >> 8, o = x & 255;
            g_W1t[x] = W1[o * 128 + i];
        } else if ((x -= 32768) < 16384) {     // O1t[m*256+j] = O1[j*64+m]
            int m = x >> 8, j = x & 255;
            g_O1t[x] = O1[j * 64 + m];
        } else if ((x -= 16384) < 65536) {     // O2t[m*256+j] = O2[j*256+m]
            int m = x >> 8, j = x & 255;
            g_O2t[x] = O2[j * 256 + m];
        } else if ((x -= 65536) < 16384) {     // O3t[k*64+c] = O3[c*256+k]
            int k = x >> 6, c = x & 63;
            g_O3t[x] = O3[c * 256 + k];
        } else {                               // B-fragments
            x -= 16384;
            int t = x >> 8, rem = x & 255;
            int n = rem >> 5, l = rem & 31;
            int k0 = t * 16 + (l & 3) * 2;
            int col = n * 8 + (l >> 2);        // output index m (mma "n")
            float w0 = W2[col * 256 + k0], w1 = W2[col * 256 + k0 + 1];
            float w8 = W2[col * 256 + k0 + 8], w9 = W2[col * 256 + k0 + 9];
            __half h0 = __float2half_rn(w0), h1 = __float2half_rn(w1);
            __half h8 = __float2half_rn(w8), h9 = __float2half_rn(w9);
            float r0 = w0 - __half2float(h0), r1 = w1 - __half2float(h1);
            float r8 = w8 - __half2float(h8), r9 = w9 - __half2float(h9);
            __half g0 = __float2half_rn(r0), g1 = __float2half_rn(r1);
            __half g8 = __float2half_rn(r8), g9 = __float2half_rn(r9);
            uint4 o;
            o.x = (u32)__half_as_ushort(h0) | ((u32)__half_as_ushort(h1) << 16);
            o.y = (u32)__half_as_ushort(h8) | ((u32)__half_as_ushort(h9) << 16);
            o.z = (u32)__half_as_ushort(g0) | ((u32)__half_as_ushort(g1) << 16);
            o.w = (u32)__half_as_ushort(g8) | ((u32)__half_as_ushort(g9) << 16);
            g_Bf[(t * 8 + n) * 32 + l] = o;
        }
    }
}

// ---------------- h1: per-node layer-1 halves -> fp16x2 ----------------
__global__ void __launch_bounds__(256) h1_kernel(const float* __restrict__ inp,
                                                 const float* __restrict__ b1) {
    const int row = blockIdx.x;
    const int tid = threadIdx.x;
    const int u = tid & 127, half = tid >> 7;   // half 0: sender, 1: receiver
    __shared__ float xs[64];
    if (tid < 64) xs[tid] = inp[row * 64 + tid];
    __syncthreads();
    float v0 = half ? b1[2 * u] : 0.f;
    float v1 = half ? b1[2 * u + 1] : 0.f;
    const float* wb = &g_W1t[half * 64 * 256 + 2 * u];
#pragma unroll 8
    for (int i = 0; i < 64; ++i) {
        float2 w = *(const float2*)(wb + i * 256);
        float x = xs[i];
        v0 = fmaf(x, w.x, v0);
        v1 = fmaf(x, w.y, v1);
    }
    u32 p = pk_h2(v1, v0);
    if (half) g_H1r16[row * 128 + u] = p;
    else      g_H1s16[row * 128 + u] = p;
}

// ---------------- edge kernel: HMMA GEMM + aggregation ----------------
// One CTA per (b,r). A = relu(H1s[s]+H1r[r]) [128e x 256k] fp16 in smem (row 528B).
// Warp w computes edges 16w..16w+15 x all 64 outputs via m16n8k16, 2 passes (W2 hi+lo).
#define A_STRIDE 528
#define OFF_A 0
#define OFF_RED 67584        // 8 warps x 68 floats
#define OFF_B2 69760
#define OFF_RTS 70016
#define SMEM_EDGE 70528

__global__ void __launch_bounds__(256) edge_kernel(const float* __restrict__ rt,
                                                   const float* __restrict__ b2) {
    extern __shared__ unsigned char sm[];
    const u32 smb = smem_u32(sm);
    const int r = blockIdx.x & 127, b = blockIdx.x >> 7;
    const int tid = threadIdx.x, w = tid >> 5, l = tid & 31;
    float* red = (float*)(sm + OFF_RED);
    float* b2s = (float*)(sm + OFF_B2);
    float* rts = (float*)(sm + OFF_RTS);

    if (tid < 64) b2s[tid] = b2[tid];
    if (tid < 128) {
        float v = 0.f;
        if (tid < 127) {
            const float* p = rt + ((size_t)(b * EDGES + r * 127 + tid)) * 2;
            v = p[0] + p[1];
        }
        rts[tid] = v;
    }

    // ---- stage A: fused add+relu in fp16x2, one STS.128 per 8 elements ----
    const u32* h1s = &g_H1s16[b * NNODE * 128];
    uint4 hr4 = *(const uint4*)&g_H1r16[(b * NNODE + r) * 128 + l * 4];
#pragma unroll 4
    for (int i = 0; i < 16; ++i) {
        int e = w * 16 + i;
        uint4 v = make_uint4(0u, 0u, 0u, 0u);
        if (e < 127) {
            int s = e + (e >= r);
            uint4 hs4 = *(const uint4*)&h1s[s * 128 + l * 4];
            v.x = frelu2(hs4.x, hr4.x);
            v.y = frelu2(hs4.y, hr4.y);
            v.z = frelu2(hs4.z, hr4.z);
            v.w = frelu2(hs4.w, hr4.w);
        }
        *(uint4*)(sm + OFF_A + e * A_STRIDE + l * 16) = v;
    }
    __syncthreads();

    // ---- mma: 16 k-steps x 8 n-tiles x 2 passes (W2 hi, W2 lo) ----
    float c[8][4];
#pragma unroll
    for (int n = 0; n < 8; ++n)
#pragma unroll
        for (int q = 0; q < 4; ++q) c[n][q] = 0.f;

    const u32 arow = smb + OFF_A + (w * 16 + (l & 15)) * A_STRIDE + ((l >> 4) * 8) * 2;
#pragma unroll 2
    for (int t = 0; t < 16; ++t) {
        u32 a0, a1, a2, a3;
        ldmatrix_x4(a0, a1, a2, a3, arow + t * 32);
#pragma unroll
        for (int n = 0; n < 8; ++n) {
            uint4 B = __ldg(&g_Bf[(t * 8 + n) * 32 + l]);
            hmma(c[n], a0, a1, a2, a3, B.x, B.y);   // hi pass
            hmma(c[n], a0, a1, a2, a3, B.z, B.w);   // lo pass
        }
    }

    // ---- epilogue: relu(C+b2)*rt, reduce over 16 edges (2 rows x 8 lane-groups) ----
    float rt0 = rts[w * 16 + (l >> 2)];
    float rt1 = rts[w * 16 + 8 + (l >> 2)];
#pragma unroll
    for (int n = 0; n < 8; ++n) {
        int n0 = n * 8 + (l & 3) * 2;
        float bb0 = b2s[n0], bb1 = b2s[n0 + 1];
        float u0 = fmaxf(c[n][0] + bb0, 0.f) * rt0 + fmaxf(c[n][2] + bb0, 0.f) * rt1;
        float u1 = fmaxf(c[n][1] + bb1, 0.f) * rt0 + fmaxf(c[n][3] + bb1, 0.f) * rt1;
#pragma unroll
        for (int off = 4; off < 32; off <<= 1) {
            u0 += __shfl_xor_sync(0xffffffffu, u0, off);
            u1 += __shfl_xor_sync(0xffffffffu, u1, off);
        }
        if (l < 4) {
            red[w * 68 + n0] = u0;
            red[w * 68 + n0 + 1] = u1;
        }
    }
    __syncthreads();
    if (tid < 64) {
        float a = 0.f;
#pragma unroll
        for (int ww = 0; ww < 8; ++ww) a += red[ww * 68 + tid];
        g_AGG[(b * NNODE + r) * 64 + tid] = a;
    }
}

// ---------------- batched node MLP: 64 -> 256 -> 256 -> 64, 16 rows/CTA ----------------
__global__ void __launch_bounds__(256) node_kernel(const float* __restrict__ o1b,
                                                   const float* __restrict__ o2b,
                                                   const float* __restrict__ o3b,
                                                   float* __restrict__ out) {
    __shared__ float aT[64][18];
    __shared__ float h0T[256][18];
    __shared__ float h1T[256][18];
    const int tid = threadIdx.x;
    const int row0 = blockIdx.x * 16;
    for (int i = tid; i < 1024; i += 256) {
        int rr = i >> 6, m = i & 63;
        aT[m][rr] = g_AGG[(row0 + rr) * 64 + m];
    }
    __syncthreads();
    {
        ull acc[8];
        ull bj = dup2(o1b[tid]);
#pragma unroll
        for (int i = 0; i < 8; ++i) acc[i] = bj;
        for (int m = 0; m < 64; ++m) {
            ull ww = dup2(g_O1t[m * 256 + tid]);
            const ull* ap = (const ull*)&aT[m][0];
#pragma unroll
            for (int i = 0; i < 8; ++i) fma2(acc[i], ww, ap[i]);
        }
#pragma unroll
        for (int i = 0; i < 8; ++i) {
            float2 f = unpk(acc[i]);
            h0T[tid][2 * i] = fmaxf(f.x, 0.f);
            h0T[tid][2 * i + 1] = fmaxf(f.y, 0.f);
        }
    }
    __syncthreads();
    {
        ull acc[8];
        ull bj = dup2(o2b[tid]);
#pragma unroll
        for (int i = 0; i < 8; ++i) acc[i] = bj;
#pragma unroll 4
        for (int m = 0; m < 256; ++m) {
            ull ww = dup2(g_O2t[m * 256 + tid]);
            const ull* ap = (const ull*)&h0T[m][0];
#pragma unroll
            for (int i = 0; i < 8; ++i) fma2(acc[i], ww, ap[i]);
        }
#pragma unroll
        for (int i = 0; i < 8; ++i) {
            float2 f = unpk(acc[i]);
            h1T[tid][2 * i] = fmaxf(f.x, 0.f);
            h1T[tid][2 * i + 1] = fmaxf(f.y, 0.f);
        }
    }
    __syncthreads();
    {
        int j = tid & 63, rg = tid >> 6;
        ull acc[2];
        ull bj = dup2(o3b[j]);
        acc[0] = bj; acc[1] = bj;
#pragma unroll 4
        for (int k = 0; k < 256; ++k) {
            ull ww = dup2(g_O3t[k * 64 + j]);
            const ull* ap = (const ull*)&h1T[k][rg * 4];
            fma2(acc[0], ww, ap[0]);
            fma2(acc[1], ww, ap[1]);
        }
        float2 f0 = unpk(acc[0]), f1 = unpk(acc[1]);
        out[(row0 + rg * 4 + 0) * 64 + j] = f0.x;
        out[(row0 + rg * 4 + 1) * 64 + j] = f0.y;
        out[(row0 + rg * 4 + 2) * 64 + j] = f1.x;
        out[(row0 + rg * 4 + 3) * 64 + j] = f1.y;
    }
}

// ---------------- launch ----------------
extern "C" void kernel_launch(void* const* d_in, const int* in_sizes, int n_in,
                              void* d_out, int out_size) {
    const float* inputs = (const float*)d_in[0];
    const float* rel_types = (const float*)d_in[3];
    const float* W1 = (const float*)d_in[4];
    const float* b1 = (const float*)d_in[5];
    const float* W2 = (const float*)d_in[6];
    const float* b2 = (const float*)d_in[7];
    const float* o1b = (const float*)d_in[9];
    const float* O1 = (const float*)d_in[8];
    const float* O2 = (const float*)d_in[10];
    const float* o2b = (const float*)d_in[11];
    const float* O3 = (const float*)d_in[12];
    const float* o3b = (const float*)d_in[13];
    float* out = (float*)d_out;

    cudaFuncSetAttribute(edge_kernel, cudaFuncAttributeMaxDynamicSharedMemorySize, SMEM_EDGE);
    prep_kernel<<<160, 256>>>(W1, W2, O1, O2, O3);
    h1_kernel<<<BATCH * NNODE, 256>>>(inputs, b1);
    edge_kernel<<<BATCH * NNODE, 256, SMEM_EDGE>>>(rel_types, b2);
    node_kernel<<<256, 256>>>(o1b, o2b, o3b, out);
}

// round 6
// speedup vs baseline: 4.1986x; 1.1525x over previous
#include <cuda_runtime.h>
#include <cuda_fp16.h>
#include <cstdint>

#define BATCH 32
#define NNODE 128
#define EDGES (NNODE * (NNODE - 1))

typedef unsigned long long ull;
typedef uint32_t u32;

// ---------------- static device scratch ----------------
__device__ float g_W1t[128 * 256];     // W1t[i*256+o] = W1[o,i]
__device__ float g_O1t[64 * 256];
__device__ float g_O2t[256 * 256];
__device__ float g_O3t[256 * 64];
__device__ uint2 g_Bf[16 * 8 * 32];    // mma B-fragments (fp16 hi only): [kstep][ntile][lane]
__device__ u32 g_H1s16[BATCH * NNODE * 128];  // fp16x2 sender-half
__device__ u32 g_H1r16[BATCH * NNODE * 128];  // fp16x2 recv-half (+b1)
__device__ float g_AGG[BATCH * NNODE * 64];

// ---------------- helpers ----------------
__device__ __forceinline__ u32 smem_u32(const void* p) {
    u32 a;
    asm("{ .reg .u64 t; cvta.to.shared.u64 t, %1; cvt.u32.u64 %0, t; }" : "=r"(a) : "l"(p));
    return a;
}
__device__ __forceinline__ ull dup2(float v) {
    ull r; unsigned u = __float_as_uint(v);
    asm("mov.b64 %0, {%1, %2};" : "=l"(r) : "r"(u), "r"(u));
    return r;
}
__device__ __forceinline__ void fma2(ull& d, ull a, ull b) {
    asm("fma.rn.f32x2 %0, %1, %2, %0;" : "+l"(d) : "l"(a), "l"(b));
}
__device__ __forceinline__ float2 unpk(ull v) {
    float2 f; asm("mov.b64 {%0, %1}, %2;" : "=f"(f.x), "=f"(f.y) : "l"(v));
    return f;
}
__device__ __forceinline__ u32 pk_h2(float hi_val, float lo_val) {
    u32 d; asm("cvt.rn.f16x2.f32 %0, %1, %2;" : "=r"(d) : "f"(hi_val), "f"(lo_val));
    return d;
}
__device__ __forceinline__ u32 frelu2(u32 hs, u32 hr) {
    u32 d;
    asm("fma.rn.relu.f16x2 %0, %1, %2, %3;" : "=r"(d) : "r"(hs), "r"(0x3C003C00u), "r"(hr));
    return d;
}
__device__ __forceinline__ void ldmatrix_x4(u32& a0, u32& a1, u32& a2, u32& a3, u32 addr) {
    asm volatile("ldmatrix.sync.aligned.m8n8.x4.shared.b16 {%0,%1,%2,%3}, [%4];"
                 : "=r"(a0), "=r"(a1), "=r"(a2), "=r"(a3) : "r"(addr));
}
__device__ __forceinline__ void hmma(float* c, u32 a0, u32 a1, u32 a2, u32 a3, u32 b0, u32 b1) {
    asm volatile(
        "mma.sync.aligned.m16n8k16.row.col.f32.f16.f16.f32 "
        "{%0,%1,%2,%3}, {%4,%5,%6,%7}, {%8,%9}, {%0,%1,%2,%3};"
        : "+f"(c[0]), "+f"(c[1]), "+f"(c[2]), "+f"(c[3])
        : "r"(a0), "r"(a1), "r"(a2), "r"(a3), "r"(b0), "r"(b1));
}

// ---------------- prep: transposes + mma B-fragments of W2 (fp16) ----------------
__global__ void prep_kernel(const float* __restrict__ W1, const float* __restrict__ W2,
                            const float* __restrict__ O1, const float* __restrict__ O2,
                            const float* __restrict__ O3) {
    const int total = 32768 + 16384 + 65536 + 16384 + 4096;
    for (int t0 = blockIdx.x * blockDim.x + threadIdx.x; t0 < total;
         t0 += gridDim.x * blockDim.x) {
        int x = t0;
        if (x < 32768) {                       // W1t[i*256+o] = W1[o*128+i]
            int i = x >> 8, o = x & 255;
            g_W1t[x] = W1[o * 128 + i];
        } else if ((x -= 32768) < 16384) {     // O1t[m*256+j] = O1[j*64+m]
            int m = x >> 8, j = x & 255;
            g_O1t[x] = O1[j * 64 + m];
        } else if ((x -= 16384) < 65536) {     // O2t[m*256+j] = O2[j*256+m]
            int m = x >> 8, j = x & 255;
            g_O2t[x] = O2[j * 256 + m];
        } else if ((x -= 65536) < 16384) {     // O3t[k*64+c] = O3[c*256+k]
            int k = x >> 6, c = x & 63;
            g_O3t[x] = O3[c * 256 + k];
        } else {                               // B-fragments (fp16 hi)
            x -= 16384;
            int t = x >> 8, rem = x & 255;
            int n = rem >> 5, l = rem & 31;
            int k0 = t * 16 + (l & 3) * 2;
            int col = n * 8 + (l >> 2);
            __half h0 = __float2half_rn(W2[col * 256 + k0]);
            __half h1 = __float2half_rn(W2[col * 256 + k0 + 1]);
            __half h8 = __float2half_rn(W2[col * 256 + k0 + 8]);
            __half h9 = __float2half_rn(W2[col * 256 + k0 + 9]);
            uint2 o;
            o.x = (u32)__half_as_ushort(h0) | ((u32)__half_as_ushort(h1) << 16);
            o.y = (u32)__half_as_ushort(h8) | ((u32)__half_as_ushort(h9) << 16);
            g_Bf[(t * 8 + n) * 32 + l] = o;
        }
    }
}

// ---------------- h1: per-node layer-1 halves -> fp16x2 ----------------
__global__ void __launch_bounds__(256) h1_kernel(const float* __restrict__ inp,
                                                 const float* __restrict__ b1) {
    const int row = blockIdx.x;
    const int tid = threadIdx.x;
    const int u = tid & 127, half = tid >> 7;
    __shared__ float xs[64];
    if (tid < 64) xs[tid] = inp[row * 64 + tid];
    __syncthreads();
    float v0 = half ? b1[2 * u] : 0.f;
    float v1 = half ? b1[2 * u + 1] : 0.f;
    const float* wb = &g_W1t[half * 64 * 256 + 2 * u];
#pragma unroll 8
    for (int i = 0; i < 64; ++i) {
        float2 w = *(const float2*)(wb + i * 256);
        float x = xs[i];
        v0 = fmaf(x, w.x, v0);
        v1 = fmaf(x, w.y, v1);
    }
    u32 p = pk_h2(v1, v0);
    if (half) g_H1r16[row * 128 + u] = p;
    else      g_H1s16[row * 128 + u] = p;
}

// ---------------- edge kernel: HMMA GEMM + aggregation ----------------
#define A_STRIDE 528
#define OFF_A 0
#define OFF_RED 67584        // 8 warps x 68 floats
#define OFF_B2 69760
#define OFF_RTS 70016
#define SMEM_EDGE 70528

__global__ void __launch_bounds__(256) edge_kernel(const float* __restrict__ rt,
                                                   const float* __restrict__ b2) {
    extern __shared__ unsigned char sm[];
    const u32 smb = smem_u32(sm);
    const int r = blockIdx.x & 127, b = blockIdx.x >> 7;
    const int tid = threadIdx.x, w = tid >> 5, l = tid & 31;
    float* red = (float*)(sm + OFF_RED);
    float* b2s = (float*)(sm + OFF_B2);
    float* rts = (float*)(sm + OFF_RTS);

    if (tid < 64) b2s[tid] = b2[tid];
    if (tid < 128) {
        float v = 0.f;
        if (tid < 127) {
            const float* p = rt + ((size_t)(b * EDGES + r * 127 + tid)) * 2;
            v = p[0] + p[1];
        }
        rts[tid] = v;
    }

    // ---- stage A: fused add+relu in fp16x2 ----
    const u32* h1s = &g_H1s16[b * NNODE * 128];
    uint4 hr4 = *(const uint4*)&g_H1r16[(b * NNODE + r) * 128 + l * 4];
#pragma unroll 4
    for (int i = 0; i < 16; ++i) {
        int e = w * 16 + i;
        uint4 v = make_uint4(0u, 0u, 0u, 0u);
        if (e < 127) {
            int s = e + (e >= r);
            uint4 hs4 = *(const uint4*)&h1s[s * 128 + l * 4];
            v.x = frelu2(hs4.x, hr4.x);
            v.y = frelu2(hs4.y, hr4.y);
            v.z = frelu2(hs4.z, hr4.z);
            v.w = frelu2(hs4.w, hr4.w);
        }
        *(uint4*)(sm + OFF_A + e * A_STRIDE + l * 16) = v;
    }
    __syncthreads();

    // ---- mma: 16 k-steps x 8 n-tiles ----
    float c[8][4];
#pragma unroll
    for (int n = 0; n < 8; ++n)
#pragma unroll
        for (int q = 0; q < 4; ++q) c[n][q] = 0.f;

    const u32 arow = smb + OFF_A + (w * 16 + (l & 15)) * A_STRIDE + ((l >> 4) * 8) * 2;
#pragma unroll 2
    for (int t = 0; t < 16; ++t) {
        u32 a0, a1, a2, a3;
        ldmatrix_x4(a0, a1, a2, a3, arow + t * 32);
#pragma unroll
        for (int n = 0; n < 8; ++n) {
            uint2 B = __ldg(&g_Bf[(t * 8 + n) * 32 + l]);
            hmma(c[n], a0, a1, a2, a3, B.x, B.y);
        }
    }

    // ---- epilogue: relu(C+b2)*rt, reduce over 16 edges ----
    float rt0 = rts[w * 16 + (l >> 2)];
    float rt1 = rts[w * 16 + 8 + (l >> 2)];
#pragma unroll
    for (int n = 0; n < 8; ++n) {
        int n0 = n * 8 + (l & 3) * 2;
        float bb0 = b2s[n0], bb1 = b2s[n0 + 1];
        float u0 = fmaxf(c[n][0] + bb0, 0.f) * rt0 + fmaxf(c[n][2] + bb0, 0.f) * rt1;
        float u1 = fmaxf(c[n][1] + bb1, 0.f) * rt0 + fmaxf(c[n][3] + bb1, 0.f) * rt1;
#pragma unroll
        for (int off = 4; off < 32; off <<= 1) {
            u0 += __shfl_xor_sync(0xffffffffu, u0, off);
            u1 += __shfl_xor_sync(0xffffffffu, u1, off);
        }
        if (l < 4) {
            red[w * 68 + n0] = u0;
            red[w * 68 + n0 + 1] = u1;
        }
    }
    __syncthreads();
    if (tid < 64) {
        float a = 0.f;
#pragma unroll
        for (int ww = 0; ww < 8; ++ww) a += red[ww * 68 + tid];
        g_AGG[(b * NNODE + r) * 64 + tid] = a;
    }
}

// ---------------- batched node MLP: 64 -> 256 -> 256 -> 64 ----------------
// 16 rows/CTA, 128 threads: thread = (jb = tid&63: 4 outputs jb+64*jj) x (rg = tid>>6: 8 rows).
// Row pitch 18 floats = 9 ull (8B-aligned for every row).
__global__ void __launch_bounds__(128) node_kernel(const float* __restrict__ o1b,
                                                   const float* __restrict__ o2b,
                                                   const float* __restrict__ o3b,
                                                   float* __restrict__ out) {
    __shared__ float aT[64][18];
    __shared__ float h0T[256][18];
    __shared__ float h1T[256][18];
    const int tid = threadIdx.x;
    const int row0 = blockIdx.x * 16;
    const int jb = tid & 63;
    const int rg = tid >> 6;

    for (int i = tid; i < 1024; i += 128) {
        int rr = i >> 6, m = i & 63;
        aT[m][rr] = g_AGG[(row0 + rr) * 64 + m];
    }
    __syncthreads();

    // ---- layer 1: 64 -> 256 ----
    {
        ull acc[4][4];
#pragma unroll
        for (int jj = 0; jj < 4; ++jj) {
            ull bj = dup2(o1b[jb + 64 * jj]);
#pragma unroll
            for (int i = 0; i < 4; ++i) acc[jj][i] = bj;
        }
#pragma unroll 4
        for (int k = 0; k < 64; ++k) {
            const ull* ap = (const ull*)&aT[k][0] + rg * 4;
            ull a0 = ap[0], a1 = ap[1], a2 = ap[2], a3 = ap[3];
#pragma unroll
            for (int jj = 0; jj < 4; ++jj) {
                ull ww = dup2(g_O1t[k * 256 + jb + 64 * jj]);
                fma2(acc[jj][0], ww, a0);
                fma2(acc[jj][1], ww, a1);
                fma2(acc[jj][2], ww, a2);
                fma2(acc[jj][3], ww, a3);
            }
        }
#pragma unroll
        for (int jj = 0; jj < 4; ++jj) {
            int j = jb + 64 * jj;
#pragma unroll
            for (int i = 0; i < 4; ++i) {
                float2 f = unpk(acc[jj][i]);
                h0T[j][rg * 8 + 2 * i] = fmaxf(f.x, 0.f);
                h0T[j][rg * 8 + 2 * i + 1] = fmaxf(f.y, 0.f);
            }
        }
    }
    __syncthreads();

    // ---- layer 2: 256 -> 256 ----
    {
        ull acc[4][4];
#pragma unroll
        for (int jj = 0; jj < 4; ++jj) {
            ull bj = dup2(o2b[jb + 64 * jj]);
#pragma unroll
            for (int i = 0; i < 4; ++i) acc[jj][i] = bj;
        }
#pragma unroll 4
        for (int k = 0; k < 256; ++k) {
            const ull* ap = (const ull*)&h0T[k][0] + rg * 4;
            ull a0 = ap[0], a1 = ap[1], a2 = ap[2], a3 = ap[3];
#pragma unroll
            for (int jj = 0; jj < 4; ++jj) {
                ull ww = dup2(g_O2t[k * 256 + jb + 64 * jj]);
                fma2(acc[jj][0], ww, a0);
                fma2(acc[jj][1], ww, a1);
                fma2(acc[jj][2], ww, a2);
                fma2(acc[jj][3], ww, a3);
            }
        }
#pragma unroll
        for (int jj = 0; jj < 4; ++jj) {
            int j = jb + 64 * jj;
#pragma unroll
            for (int i = 0; i < 4; ++i) {
                float2 f = unpk(acc[jj][i]);
                h1T[j][rg * 8 + 2 * i] = fmaxf(f.x, 0.f);
                h1T[j][rg * 8 + 2 * i + 1] = fmaxf(f.y, 0.f);
            }
        }
    }
    __syncthreads();

    // ---- layer 3: 256 -> 64 ----
    {
        ull acc[4];
        ull bj = dup2(o3b[jb]);
#pragma unroll
        for (int i = 0; i < 4; ++i) acc[i] = bj;
#pragma unroll 4
        for (int k = 0; k < 256; ++k) {
            const ull* ap = (const ull*)&h1T[k][0] + rg * 4;
            ull ww = dup2(g_O3t[k * 64 + jb]);
            fma2(acc[0], ww, ap[0]);
            fma2(acc[1], ww, ap[1]);
            fma2(acc[2], ww, ap[2]);
            fma2(acc[3], ww, ap[3]);
        }
#pragma unroll
        for (int i = 0; i < 4; ++i) {
            float2 f = unpk(acc[i]);
            out[(row0 + rg * 8 + 2 * i) * 64 + jb] = f.x;
            out[(row0 + rg * 8 + 2 * i + 1) * 64 + jb] = f.y;
        }
    }
}

// ---------------- launch ----------------
extern "C" void kernel_launch(void* const* d_in, const int* in_sizes, int n_in,
                              void* d_out, int out_size) {
    const float* inputs = (const float*)d_in[0];
    const float* rel_types = (const float*)d_in[3];
    const float* W1 = (const float*)d_in[4];
    const float* b1 = (const float*)d_in[5];
    const float* W2 = (const float*)d_in[6];
    const float* b2 = (const float*)d_in[7];
    const float* O1 = (const float*)d_in[8];
    const float* o1b = (const float*)d_in[9];
    const float* O2 = (const float*)d_in[10];
    const float* o2b = (const float*)d_in[11];
    const float* O3 = (const float*)d_in[12];
    const float* o3b = (const float*)d_in[13];
    float* out = (float*)d_out;

    cudaFuncSetAttribute(edge_kernel, cudaFuncAttributeMaxDynamicSharedMemorySize, SMEM_EDGE);
    prep_kernel<<<160, 256>>>(W1, W2, O1, O2, O3);
    h1_kernel<<<BATCH * NNODE, 256>>>(inputs, b1);
    edge_kernel<<<BATCH * NNODE, 256, SMEM_EDGE>>>(rel_types, b2);
    node_kernel<<<256, 128>>>(o1b, o2b, o3b, out);
}

// round 7
// speedup vs baseline: 4.5778x; 1.0903x over previous
#include <cuda_runtime.h>
#include <cuda_fp16.h>
#include <cstdint>

#define BATCH 32
#define NNODE 128
#define EDGES (NNODE * (NNODE - 1))

typedef unsigned long long ull;
typedef uint32_t u32;

// ---------------- static device scratch ----------------
__device__ float g_W1t[128 * 256];            // W1t[i*256+o] = W1[o,i]
__device__ uint2 g_Bf[16 * 8 * 32];           // W2  B-frags: [kstep][ntile][lane]
__device__ uint2 g_O1f[4 * 32 * 32];          // O1  B-frags (K=64,  N=256)
__device__ uint2 g_O2f[16 * 32 * 32];         // O2  B-frags (K=256, N=256)
__device__ uint2 g_O3f[16 * 8 * 32];          // O3  B-frags (K=256, N=64)
__device__ u32 g_H1s16[BATCH * NNODE * 128];  // fp16x2 sender-half
__device__ u32 g_H1r16[BATCH * NNODE * 128];  // fp16x2 recv-half (+b1)
__device__ float g_AGG[BATCH * NNODE * 64];

// ---------------- helpers ----------------
__device__ __forceinline__ u32 smem_u32(const void* p) {
    u32 a;
    asm("{ .reg .u64 t; cvta.to.shared.u64 t, %1; cvt.u32.u64 %0, t; }" : "=r"(a) : "l"(p));
    return a;
}
__device__ __forceinline__ u32 pk_h2(float hi_val, float lo_val) {
    u32 d; asm("cvt.rn.f16x2.f32 %0, %1, %2;" : "=r"(d) : "f"(hi_val), "f"(lo_val));
    return d;
}
__device__ __forceinline__ u32 frelu2(u32 hs, u32 hr) {
    u32 d;
    asm("fma.rn.relu.f16x2 %0, %1, %2, %3;" : "=r"(d) : "r"(hs), "r"(0x3C003C00u), "r"(hr));
    return d;
}
__device__ __forceinline__ void ldmatrix_x4(u32& a0, u32& a1, u32& a2, u32& a3, u32 addr) {
    asm volatile("ldmatrix.sync.aligned.m8n8.x4.shared.b16 {%0,%1,%2,%3}, [%4];"
                 : "=r"(a0), "=r"(a1), "=r"(a2), "=r"(a3) : "r"(addr));
}
__device__ __forceinline__ void hmma(float* c, u32 a0, u32 a1, u32 a2, u32 a3, u32 b0, u32 b1) {
    asm volatile(
        "mma.sync.aligned.m16n8k16.row.col.f32.f16.f16.f32 "
        "{%0,%1,%2,%3}, {%4,%5,%6,%7}, {%8,%9}, {%0,%1,%2,%3};"
        : "+f"(c[0]), "+f"(c[1]), "+f"(c[2]), "+f"(c[3])
        : "r"(a0), "r"(a1), "r"(a2), "r"(a3), "r"(b0), "r"(b1));
}
// build one B-fragment uint2 for row-major weight W[N][K]
__device__ __forceinline__ uint2 mk_bfrag(const float* W, int K, int t, int nt, int l) {
    int k0 = t * 16 + (l & 3) * 2;
    int col = nt * 8 + (l >> 2);
    __half h0 = __float2half_rn(W[col * K + k0]);
    __half h1 = __float2half_rn(W[col * K + k0 + 1]);
    __half h8 = __float2half_rn(W[col * K + k0 + 8]);
    __half h9 = __float2half_rn(W[col * K + k0 + 9]);
    uint2 o;
    o.x = (u32)__half_as_ushort(h0) | ((u32)__half_as_ushort(h1) << 16);
    o.y = (u32)__half_as_ushort(h8) | ((u32)__half_as_ushort(h9) << 16);
    return o;
}

// ---------------- prep: W1 transpose + all mma B-fragments ----------------
__global__ void prep_kernel(const float* __restrict__ W1, const float* __restrict__ W2,
                            const float* __restrict__ O1, const float* __restrict__ O2,
                            const float* __restrict__ O3) {
    const int total = 32768 + 4096 + 4096 + 16384 + 4096;
    for (int t0 = blockIdx.x * blockDim.x + threadIdx.x; t0 < total;
         t0 += gridDim.x * blockDim.x) {
        int x = t0;
        if (x < 32768) {                       // W1t[i*256+o] = W1[o*128+i]
            int i = x >> 8, o = x & 255;
            g_W1t[x] = W1[o * 128 + i];
        } else if ((x -= 32768) < 4096) {      // W2 frags: 16 ksteps x 8 ntiles
            int t = x >> 8, nt = (x >> 5) & 7, l = x & 31;
            g_Bf[x] = mk_bfrag(W2, 256, t, nt, l);
        } else if ((x -= 4096) < 4096) {       // O1 frags: 4 ksteps x 32 ntiles
            int t = x >> 10, nt = (x >> 5) & 31, l = x & 31;
            g_O1f[x] = mk_bfrag(O1, 64, t, nt, l);
        } else if ((x -= 4096) < 16384) {      // O2 frags: 16 x 32
            int t = x >> 10, nt = (x >> 5) & 31, l = x & 31;
            g_O2f[x] = mk_bfrag(O2, 256, t, nt, l);
        } else {                               // O3 frags: 16 x 8
            x -= 16384;
            int t = x >> 8, nt = (x >> 5) & 7, l = x & 31;
            g_O3f[x] = mk_bfrag(O3, 256, t, nt, l);
        }
    }
}

// ---------------- h1: per-node layer-1 halves -> fp16x2 ----------------
__global__ void __launch_bounds__(256) h1_kernel(const float* __restrict__ inp,
                                                 const float* __restrict__ b1) {
    const int row = blockIdx.x;
    const int tid = threadIdx.x;
    const int u = tid & 127, half = tid >> 7;
    __shared__ float xs[64];
    if (tid < 64) xs[tid] = inp[row * 64 + tid];
    __syncthreads();
    float v0 = half ? b1[2 * u] : 0.f;
    float v1 = half ? b1[2 * u + 1] : 0.f;
    const float* wb = &g_W1t[half * 64 * 256 + 2 * u];
#pragma unroll 8
    for (int i = 0; i < 64; ++i) {
        float2 w = *(const float2*)(wb + i * 256);
        float x = xs[i];
        v0 = fmaf(x, w.x, v0);
        v1 = fmaf(x, w.y, v1);
    }
    u32 p = pk_h2(v1, v0);
    if (half) g_H1r16[row * 128 + u] = p;
    else      g_H1s16[row * 128 + u] = p;
}

// ---------------- edge kernel: HMMA GEMM + aggregation ----------------
#define A_STRIDE 528
#define OFF_A 0
#define OFF_RED 67584        // 8 warps x 68 floats
#define OFF_B2 69760
#define OFF_RTS 70016
#define SMEM_EDGE 70528

__global__ void __launch_bounds__(256) edge_kernel(const float* __restrict__ rt,
                                                   const float* __restrict__ b2) {
    extern __shared__ unsigned char sm[];
    const u32 smb = smem_u32(sm);
    const int r = blockIdx.x & 127, b = blockIdx.x >> 7;
    const int tid = threadIdx.x, w = tid >> 5, l = tid & 31;
    float* red = (float*)(sm + OFF_RED);
    float* b2s = (float*)(sm + OFF_B2);
    float* rts = (float*)(sm + OFF_RTS);

    if (tid < 64) b2s[tid] = b2[tid];
    if (tid < 128) {
        float v = 0.f;
        if (tid < 127) {
            const float* p = rt + ((size_t)(b * EDGES + r * 127 + tid)) * 2;
            v = p[0] + p[1];
        }
        rts[tid] = v;
    }

    // ---- stage A: fused add+relu in fp16x2 ----
    const u32* h1s = &g_H1s16[b * NNODE * 128];
    uint4 hr4 = *(const uint4*)&g_H1r16[(b * NNODE + r) * 128 + l * 4];
#pragma unroll 4
    for (int i = 0; i < 16; ++i) {
        int e = w * 16 + i;
        uint4 v = make_uint4(0u, 0u, 0u, 0u);
        if (e < 127) {
            int s = e + (e >= r);
            uint4 hs4 = *(const uint4*)&h1s[s * 128 + l * 4];
            v.x = frelu2(hs4.x, hr4.x);
            v.y = frelu2(hs4.y, hr4.y);
            v.z = frelu2(hs4.z, hr4.z);
            v.w = frelu2(hs4.w, hr4.w);
        }
        *(uint4*)(sm + OFF_A + e * A_STRIDE + l * 16) = v;
    }
    __syncthreads();

    // ---- mma: 16 k-steps x 8 n-tiles ----
    float c[8][4];
#pragma unroll
    for (int n = 0; n < 8; ++n)
#pragma unroll
        for (int q = 0; q < 4; ++q) c[n][q] = 0.f;

    const u32 arow = smb + OFF_A + (w * 16 + (l & 15)) * A_STRIDE + ((l >> 4) * 8) * 2;
#pragma unroll 2
    for (int t = 0; t < 16; ++t) {
        u32 a0, a1, a2, a3;
        ldmatrix_x4(a0, a1, a2, a3, arow + t * 32);
#pragma unroll
        for (int n = 0; n < 8; ++n) {
            uint2 B = __ldg(&g_Bf[(t * 8 + n) * 32 + l]);
            hmma(c[n], a0, a1, a2, a3, B.x, B.y);
        }
    }

    // ---- epilogue: relu(C+b2)*rt, reduce over 16 edges ----
    float rt0 = rts[w * 16 + (l >> 2)];
    float rt1 = rts[w * 16 + 8 + (l >> 2)];
#pragma unroll
    for (int n = 0; n < 8; ++n) {
        int n0 = n * 8 + (l & 3) * 2;
        float bb0 = b2s[n0], bb1 = b2s[n0 + 1];
        float u0 = fmaxf(c[n][0] + bb0, 0.f) * rt0 + fmaxf(c[n][2] + bb0, 0.f) * rt1;
        float u1 = fmaxf(c[n][1] + bb1, 0.f) * rt0 + fmaxf(c[n][3] + bb1, 0.f) * rt1;
#pragma unroll
        for (int off = 4; off < 32; off <<= 1) {
            u0 += __shfl_xor_sync(0xffffffffu, u0, off);
            u1 += __shfl_xor_sync(0xffffffffu, u1, off);
        }
        if (l < 4) {
            red[w * 68 + n0] = u0;
            red[w * 68 + n0 + 1] = u1;
        }
    }
    __syncthreads();
    if (tid < 64) {
        float a = 0.f;
#pragma unroll
        for (int ww = 0; ww < 8; ++ww) a += red[ww * 68 + tid];
        g_AGG[(b * NNODE + r) * 64 + tid] = a;
    }
}

// ---------------- node kernel: HMMA MLP 64 -> 256 -> 256 -> 64 ----------------
// 16 rows/CTA, 4 warps. Warp w owns output cols [w*64, w*64+64) in layers 1-2
// and [w*16, w*16+16) in layer 3. Activations in fp16 smem tiles, 528B row stride.
#define NOFF_A0 0
#define NOFF_A1 8448
#define SMEM_NODE 16896

__global__ void __launch_bounds__(128) node_kernel(const float* __restrict__ o1b,
                                                   const float* __restrict__ o2b,
                                                   const float* __restrict__ o3b,
                                                   float* __restrict__ out) {
    extern __shared__ unsigned char sm[];
    const u32 smb = smem_u32(sm);
    const int tid = threadIdx.x, w = tid >> 5, l = tid & 31;
    const int row0 = blockIdx.x * 16;

    // ---- load agg [16 x 64] f32 -> fp16 tile A0 ----
    for (int i = tid; i < 512; i += 128) {
        int rr = i >> 5, cp = i & 31;
        float2 v = *(const float2*)&g_AGG[(row0 + rr) * 64 + cp * 2];
        *(u32*)(sm + NOFF_A0 + rr * A_STRIDE + cp * 4) = pk_h2(v.y, v.x);
    }
    __syncthreads();

    const u32 arow_base = smb + (l & 15) * A_STRIDE + ((l >> 4) * 8) * 2;
    const int ra = l >> 2, cshift = (l & 3) * 2;

    // ---- layer 1: K=64 (4 ksteps), N=256 ----
    {
        float c[8][4];
#pragma unroll
        for (int n = 0; n < 8; ++n)
#pragma unroll
            for (int q = 0; q < 4; ++q) c[n][q] = 0.f;
        const u32 arow = arow_base + NOFF_A0;
#pragma unroll
        for (int t = 0; t < 4; ++t) {
            u32 a0, a1, a2, a3;
            ldmatrix_x4(a0, a1, a2, a3, arow + t * 32);
#pragma unroll
            for (int n = 0; n < 8; ++n) {
                uint2 B = __ldg(&g_O1f[(t * 32 + w * 8 + n) * 32 + l]);
                hmma(c[n], a0, a1, a2, a3, B.x, B.y);
            }
        }
        __syncthreads();   // A0 fully consumed before A1 written? (A1 distinct; sync protects nothing here but cheap) 
#pragma unroll
        for (int n = 0; n < 8; ++n) {
            int col = w * 64 + n * 8 + cshift;
            float bb0 = __ldg(&o1b[col]), bb1 = __ldg(&o1b[col + 1]);
            *(u32*)(sm + NOFF_A1 + ra * A_STRIDE + col * 2) =
                pk_h2(fmaxf(c[n][1] + bb1, 0.f), fmaxf(c[n][0] + bb0, 0.f));
            *(u32*)(sm + NOFF_A1 + (ra + 8) * A_STRIDE + col * 2) =
                pk_h2(fmaxf(c[n][3] + bb1, 0.f), fmaxf(c[n][2] + bb0, 0.f));
        }
    }
    __syncthreads();

    // ---- layer 2: K=256 (16 ksteps), N=256 ----
    {
        float c[8][4];
#pragma unroll
        for (int n = 0; n < 8; ++n)
#pragma unroll
            for (int q = 0; q < 4; ++q) c[n][q] = 0.f;
        const u32 arow = arow_base + NOFF_A1;
#pragma unroll 4
        for (int t = 0; t < 16; ++t) {
            u32 a0, a1, a2, a3;
            ldmatrix_x4(a0, a1, a2, a3, arow + t * 32);
#pragma unroll
            for (int n = 0; n < 8; ++n) {
                uint2 B = __ldg(&g_O2f[(t * 32 + w * 8 + n) * 32 + l]);
                hmma(c[n], a0, a1, a2, a3, B.x, B.y);
            }
        }
        __syncthreads();   // everyone done reading A1... and A0 free for reuse
#pragma unroll
        for (int n = 0; n < 8; ++n) {
            int col = w * 64 + n * 8 + cshift;
            float bb0 = __ldg(&o2b[col]), bb1 = __ldg(&o2b[col + 1]);
            *(u32*)(sm + NOFF_A0 + ra * A_STRIDE + col * 2) =
                pk_h2(fmaxf(c[n][1] + bb1, 0.f), fmaxf(c[n][0] + bb0, 0.f));
            *(u32*)(sm + NOFF_A0 + (ra + 8) * A_STRIDE + col * 2) =
                pk_h2(fmaxf(c[n][3] + bb1, 0.f), fmaxf(c[n][2] + bb0, 0.f));
        }
    }
    __syncthreads();

    // ---- layer 3: K=256 (16 ksteps), N=64; warp w -> cols w*16..w*16+15 ----
    {
        float c[2][4];
#pragma unroll
        for (int n = 0; n < 2; ++n)
#pragma unroll
            for (int q = 0; q < 4; ++q) c[n][q] = 0.f;
        const u32 arow = arow_base + NOFF_A0;
#pragma unroll 4
        for (int t = 0; t < 16; ++t) {
            u32 a0, a1, a2, a3;
            ldmatrix_x4(a0, a1, a2, a3, arow + t * 32);
#pragma unroll
            for (int n = 0; n < 2; ++n) {
                uint2 B = __ldg(&g_O3f[(t * 8 + w * 2 + n) * 32 + l]);
                hmma(c[n], a0, a1, a2, a3, B.x, B.y);
            }
        }
#pragma unroll
        for (int n = 0; n < 2; ++n) {
            int col = w * 16 + n * 8 + cshift;
            float bb0 = __ldg(&o3b[col]), bb1 = __ldg(&o3b[col + 1]);
            *(float2*)&out[(row0 + ra) * 64 + col] = make_float2(c[n][0] + bb0, c[n][1] + bb1);
            *(float2*)&out[(row0 + ra + 8) * 64 + col] = make_float2(c[n][2] + bb0, c[n][3] + bb1);
        }
    }
}

// ---------------- launch ----------------
extern "C" void kernel_launch(void* const* d_in, const int* in_sizes, int n_in,
                              void* d_out, int out_size) {
    const float* inputs = (const float*)d_in[0];
    const float* rel_types = (const float*)d_in[3];
    const float* W1 = (const float*)d_in[4];
    const float* b1 = (const float*)d_in[5];
    const float* W2 = (const float*)d_in[6];
    const float* b2 = (const float*)d_in[7];
    const float* O1 = (const float*)d_in[8];
    const float* o1b = (const float*)d_in[9];
    const float* O2 = (const float*)d_in[10];
    const float* o2b = (const float*)d_in[11];
    const float* O3 = (const float*)d_in[12];
    const float* o3b = (const float*)d_in[13];
    float* out = (float*)d_out;

    cudaFuncSetAttribute(edge_kernel, cudaFuncAttributeMaxDynamicSharedMemorySize, SMEM_EDGE);
    cudaFuncSetAttribute(node_kernel, cudaFuncAttributeMaxDynamicSharedMemorySize, SMEM_NODE);
    prep_kernel<<<160, 256>>>(W1, W2, O1, O2, O3);
    h1_kernel<<<BATCH * NNODE, 256>>>(inputs, b1);
    edge_kernel<<<BATCH * NNODE, 256, SMEM_EDGE>>>(rel_types, b2);
    node_kernel<<<256, 128, SMEM_NODE>>>(o1b, o2b, o3b, out);
}

// round 8
// speedup vs baseline: 5.6147x; 1.2265x over previous
#include <cuda_runtime.h>
#include <cuda_fp16.h>
#include <cstdint>

#define BATCH 32
#define NNODE 128
#define EDGES (NNODE * (NNODE - 1))

typedef unsigned long long ull;
typedef uint32_t u32;

// ---------------- static device scratch ----------------
__device__ float g_W1t[128 * 256];            // W1t[i*256+o] = W1[o,i]
__device__ uint2 g_Bf[16 * 8 * 32];           // W2  B-frags: [kstep][ntile][lane]
__device__ uint2 g_O1f[4 * 32 * 32];          // O1  B-frags (K=64,  N=256)
__device__ uint2 g_O2f[16 * 32 * 32];         // O2  B-frags (K=256, N=256)
__device__ uint2 g_O3f[16 * 8 * 32];          // O3  B-frags (K=256, N=64)
__device__ u32 g_H1s16[BATCH * NNODE * 128];  // fp16x2 sender-half
__device__ u32 g_H1r16[BATCH * NNODE * 128];  // fp16x2 recv-half (+b1)
__device__ float g_AGG[BATCH * NNODE * 64];

// ---------------- helpers ----------------
__device__ __forceinline__ u32 smem_u32(const void* p) {
    u32 a;
    asm("{ .reg .u64 t; cvta.to.shared.u64 t, %1; cvt.u32.u64 %0, t; }" : "=r"(a) : "l"(p));
    return a;
}
__device__ __forceinline__ u32 pk_h2(float hi_val, float lo_val) {
    u32 d; asm("cvt.rn.f16x2.f32 %0, %1, %2;" : "=r"(d) : "f"(hi_val), "f"(lo_val));
    return d;
}
__device__ __forceinline__ u32 frelu2(u32 hs, u32 hr) {
    u32 d;
    asm("fma.rn.relu.f16x2 %0, %1, %2, %3;" : "=r"(d) : "r"(hs), "r"(0x3C003C00u), "r"(hr));
    return d;
}
__device__ __forceinline__ void ldmatrix_x4(u32& a0, u32& a1, u32& a2, u32& a3, u32 addr) {
    asm volatile("ldmatrix.sync.aligned.m8n8.x4.shared.b16 {%0,%1,%2,%3}, [%4];"
                 : "=r"(a0), "=r"(a1), "=r"(a2), "=r"(a3) : "r"(addr));
}
__device__ __forceinline__ void hmma(float* c, u32 a0, u32 a1, u32 a2, u32 a3, u32 b0, u32 b1) {
    asm volatile(
        "mma.sync.aligned.m16n8k16.row.col.f32.f16.f16.f32 "
        "{%0,%1,%2,%3}, {%4,%5,%6,%7}, {%8,%9}, {%0,%1,%2,%3};"
        : "+f"(c[0]), "+f"(c[1]), "+f"(c[2]), "+f"(c[3])
        : "r"(a0), "r"(a1), "r"(a2), "r"(a3), "r"(b0), "r"(b1));
}
// build one B-fragment uint2 for row-major weight W[N][K]
__device__ __forceinline__ uint2 mk_bfrag(const float* W, int K, int t, int nt, int l) {
    int k0 = t * 16 + (l & 3) * 2;
    int col = nt * 8 + (l >> 2);
    __half h0 = __float2half_rn(W[col * K + k0]);
    __half h1 = __float2half_rn(W[col * K + k0 + 1]);
    __half h8 = __float2half_rn(W[col * K + k0 + 8]);
    __half h9 = __float2half_rn(W[col * K + k0 + 9]);
    uint2 o;
    o.x = (u32)__half_as_ushort(h0) | ((u32)__half_as_ushort(h1) << 16);
    o.y = (u32)__half_as_ushort(h8) | ((u32)__half_as_ushort(h9) << 16);
    return o;
}

// ---------------- prep: W1 transpose + all mma B-fragments ----------------
__global__ void prep_kernel(const float* __restrict__ W1, const float* __restrict__ W2,
                            const float* __restrict__ O1, const float* __restrict__ O2,
                            const float* __restrict__ O3) {
    const int total = 32768 + 4096 + 4096 + 16384 + 4096;
    for (int t0 = blockIdx.x * blockDim.x + threadIdx.x; t0 < total;
         t0 += gridDim.x * blockDim.x) {
        int x = t0;
        if (x < 32768) {
            int i = x >> 8, o = x & 255;
            g_W1t[x] = W1[o * 128 + i];
        } else if ((x -= 32768) < 4096) {      // W2 frags: 16 ksteps x 8 ntiles
            int t = x >> 8, nt = (x >> 5) & 7, l = x & 31;
            g_Bf[x] = mk_bfrag(W2, 256, t, nt, l);
        } else if ((x -= 4096) < 4096) {       // O1 frags: 4 ksteps x 32 ntiles
            int t = x >> 10, nt = (x >> 5) & 31, l = x & 31;
            g_O1f[x] = mk_bfrag(O1, 64, t, nt, l);
        } else if ((x -= 4096) < 16384) {      // O2 frags: 16 x 32
            int t = x >> 10, nt = (x >> 5) & 31, l = x & 31;
            g_O2f[x] = mk_bfrag(O2, 256, t, nt, l);
        } else {                               // O3 frags: 16 x 8
            x -= 16384;
            int t = x >> 8, nt = (x >> 5) & 7, l = x & 31;
            g_O3f[x] = mk_bfrag(O3, 256, t, nt, l);
        }
    }
}

// ---------------- h1: per-node layer-1 halves -> fp16x2 ----------------
__global__ void __launch_bounds__(256) h1_kernel(const float* __restrict__ inp,
                                                 const float* __restrict__ b1) {
    const int row = blockIdx.x;
    const int tid = threadIdx.x;
    const int u = tid & 127, half = tid >> 7;
    __shared__ float xs[64];
    if (tid < 64) xs[tid] = inp[row * 64 + tid];
    __syncthreads();
    float v0 = half ? b1[2 * u] : 0.f;
    float v1 = half ? b1[2 * u + 1] : 0.f;
    const float* wb = &g_W1t[half * 64 * 256 + 2 * u];
#pragma unroll 8
    for (int i = 0; i < 64; ++i) {
        float2 w = *(const float2*)(wb + i * 256);
        float x = xs[i];
        v0 = fmaf(x, w.x, v0);
        v1 = fmaf(x, w.y, v1);
    }
    u32 p = pk_h2(v1, v0);
    if (half) g_H1r16[row * 128 + u] = p;
    else      g_H1s16[row * 128 + u] = p;
}

// ---------------- edge kernel: HMMA GEMM + aggregation ----------------
#define A_STRIDE 528
#define OFF_A 0
#define OFF_RED 67584        // 8 warps x 68 floats
#define OFF_B2 69760
#define OFF_RTS 70016
#define SMEM_EDGE 70528

__global__ void __launch_bounds__(256) edge_kernel(const float* __restrict__ rt,
                                                   const float* __restrict__ b2) {
    extern __shared__ unsigned char sm[];
    const u32 smb = smem_u32(sm);
    const int r = blockIdx.x & 127, b = blockIdx.x >> 7;
    const int tid = threadIdx.x, w = tid >> 5, l = tid & 31;
    float* red = (float*)(sm + OFF_RED);
    float* b2s = (float*)(sm + OFF_B2);
    float* rts = (float*)(sm + OFF_RTS);

    if (tid < 64) b2s[tid] = b2[tid];
    if (tid < 128) {
        float v = 0.f;
        if (tid < 127) {
            const float* p = rt + ((size_t)(b * EDGES + r * 127 + tid)) * 2;
            v = p[0] + p[1];
        }
        rts[tid] = v;
    }

    // ---- stage A: fused add+relu in fp16x2 ----
    const u32* h1s = &g_H1s16[b * NNODE * 128];
    uint4 hr4 = *(const uint4*)&g_H1r16[(b * NNODE + r) * 128 + l * 4];
#pragma unroll 4
    for (int i = 0; i < 16; ++i) {
        int e = w * 16 + i;
        uint4 v = make_uint4(0u, 0u, 0u, 0u);
        if (e < 127) {
            int s = e + (e >= r);
            uint4 hs4 = *(const uint4*)&h1s[s * 128 + l * 4];
            v.x = frelu2(hs4.x, hr4.x);
            v.y = frelu2(hs4.y, hr4.y);
            v.z = frelu2(hs4.z, hr4.z);
            v.w = frelu2(hs4.w, hr4.w);
        }
        *(uint4*)(sm + OFF_A + e * A_STRIDE + l * 16) = v;
    }
    __syncthreads();

    // ---- mma: 16 k-steps x 8 n-tiles ----
    float c[8][4];
#pragma unroll
    for (int n = 0; n < 8; ++n)
#pragma unroll
        for (int q = 0; q < 4; ++q) c[n][q] = 0.f;

    const u32 arow = smb + OFF_A + (w * 16 + (l & 15)) * A_STRIDE + ((l >> 4) * 8) * 2;
#pragma unroll 2
    for (int t = 0; t < 16; ++t) {
        u32 a0, a1, a2, a3;
        ldmatrix_x4(a0, a1, a2, a3, arow + t * 32);
#pragma unroll
        for (int n = 0; n < 8; ++n) {
            uint2 B = __ldg(&g_Bf[(t * 8 + n) * 32 + l]);
            hmma(c[n], a0, a1, a2, a3, B.x, B.y);
        }
    }

    // ---- epilogue: relu(C+b2)*rt, reduce over 16 edges ----
    float rt0 = rts[w * 16 + (l >> 2)];
    float rt1 = rts[w * 16 + 8 + (l >> 2)];
#pragma unroll
    for (int n = 0; n < 8; ++n) {
        int n0 = n * 8 + (l & 3) * 2;
        float bb0 = b2s[n0], bb1 = b2s[n0 + 1];
        float u0 = fmaxf(c[n][0] + bb0, 0.f) * rt0 + fmaxf(c[n][2] + bb0, 0.f) * rt1;
        float u1 = fmaxf(c[n][1] + bb1, 0.f) * rt0 + fmaxf(c[n][3] + bb1, 0.f) * rt1;
#pragma unroll
        for (int off = 4; off < 32; off <<= 1) {
            u0 += __shfl_xor_sync(0xffffffffu, u0, off);
            u1 += __shfl_xor_sync(0xffffffffu, u1, off);
        }
        if (l < 4) {
            red[w * 68 + n0] = u0;
            red[w * 68 + n0 + 1] = u1;
        }
    }
    __syncthreads();
    if (tid < 64) {
        float a = 0.f;
#pragma unroll
        for (int ww = 0; ww < 8; ++ww) a += red[ww * 68 + tid];
        g_AGG[(b * NNODE + r) * 64 + tid] = a;
    }
}

// ---------------- node kernel: HMMA MLP 64 -> 256 -> 256 -> 64 ----------------
// 16 rows/CTA, 8 warps. Layers 1-2: warp w -> 4 ntiles = cols [w*32, w*32+32).
// Layer 3: warp w -> ntile w = cols [w*8, w*8+8). B-frags prefetched one k-step ahead.
#define NOFF_A0 0
#define NOFF_A1 8448
#define SMEM_NODE 16896

__global__ void __launch_bounds__(256) node_kernel(const float* __restrict__ o1b,
                                                   const float* __restrict__ o2b,
                                                   const float* __restrict__ o3b,
                                                   float* __restrict__ out) {
    extern __shared__ unsigned char sm[];
    const u32 smb = smem_u32(sm);
    const int tid = threadIdx.x, w = tid >> 5, l = tid & 31;
    const int row0 = blockIdx.x * 16;

    // ---- load agg [16 x 64] f32 -> fp16 tile A0 ----
    for (int i = tid; i < 512; i += 256) {
        int rr = i >> 5, cp = i & 31;
        float2 v = *(const float2*)&g_AGG[(row0 + rr) * 64 + cp * 2];
        *(u32*)(sm + NOFF_A0 + rr * A_STRIDE + cp * 4) = pk_h2(v.y, v.x);
    }
    __syncthreads();

    const u32 arow_base = smb + (l & 15) * A_STRIDE + ((l >> 4) * 8) * 2;
    const int ra = l >> 2, cshift = (l & 3) * 2;

    // ---- layer 1: K=64 (4 ksteps), N=256, warp w -> ntiles w*4..w*4+3 ----
    {
        float c[4][4];
#pragma unroll
        for (int n = 0; n < 4; ++n)
#pragma unroll
            for (int q = 0; q < 4; ++q) c[n][q] = 0.f;
        const u32 arow = arow_base + NOFF_A0;
        uint2 Bp[4];
#pragma unroll
        for (int n = 0; n < 4; ++n) Bp[n] = __ldg(&g_O1f[(w * 4 + n) * 32 + l]);
#pragma unroll
        for (int t = 0; t < 4; ++t) {
            u32 a0, a1, a2, a3;
            ldmatrix_x4(a0, a1, a2, a3, arow + t * 32);
            uint2 Bn[4];
            if (t < 3) {
#pragma unroll
                for (int n = 0; n < 4; ++n)
                    Bn[n] = __ldg(&g_O1f[((t + 1) * 32 + w * 4 + n) * 32 + l]);
            }
#pragma unroll
            for (int n = 0; n < 4; ++n) hmma(c[n], a0, a1, a2, a3, Bp[n].x, Bp[n].y);
#pragma unroll
            for (int n = 0; n < 4; ++n) Bp[n] = Bn[n];
        }
        __syncthreads();
#pragma unroll
        for (int n = 0; n < 4; ++n) {
            int col = w * 32 + n * 8 + cshift;
            float bb0 = __ldg(&o1b[col]), bb1 = __ldg(&o1b[col + 1]);
            *(u32*)(sm + NOFF_A1 + ra * A_STRIDE + col * 2) =
                pk_h2(fmaxf(c[n][1] + bb1, 0.f), fmaxf(c[n][0] + bb0, 0.f));
            *(u32*)(sm + NOFF_A1 + (ra + 8) * A_STRIDE + col * 2) =
                pk_h2(fmaxf(c[n][3] + bb1, 0.f), fmaxf(c[n][2] + bb0, 0.f));
        }
    }
    __syncthreads();

    // ---- layer 2: K=256 (16 ksteps), N=256 ----
    {
        float c[4][4];
#pragma unroll
        for (int n = 0; n < 4; ++n)
#pragma unroll
            for (int q = 0; q < 4; ++q) c[n][q] = 0.f;
        const u32 arow = arow_base + NOFF_A1;
        uint2 Bp[4];
#pragma unroll
        for (int n = 0; n < 4; ++n) Bp[n] = __ldg(&g_O2f[(w * 4 + n) * 32 + l]);
#pragma unroll 4
        for (int t = 0; t < 16; ++t) {
            u32 a0, a1, a2, a3;
            ldmatrix_x4(a0, a1, a2, a3, arow + t * 32);
            uint2 Bn[4];
            if (t < 15) {
#pragma unroll
                for (int n = 0; n < 4; ++n)
                    Bn[n] = __ldg(&g_O2f[((t + 1) * 32 + w * 4 + n) * 32 + l]);
            }
#pragma unroll
            for (int n = 0; n < 4; ++n) hmma(c[n], a0, a1, a2, a3, Bp[n].x, Bp[n].y);
#pragma unroll
            for (int n = 0; n < 4; ++n) Bp[n] = Bn[n];
        }
        __syncthreads();
#pragma unroll
        for (int n = 0; n < 4; ++n) {
            int col = w * 32 + n * 8 + cshift;
            float bb0 = __ldg(&o2b[col]), bb1 = __ldg(&o2b[col + 1]);
            *(u32*)(sm + NOFF_A0 + ra * A_STRIDE + col * 2) =
                pk_h2(fmaxf(c[n][1] + bb1, 0.f), fmaxf(c[n][0] + bb0, 0.f));
            *(u32*)(sm + NOFF_A0 + (ra + 8) * A_STRIDE + col * 2) =
                pk_h2(fmaxf(c[n][3] + bb1, 0.f), fmaxf(c[n][2] + bb0, 0.f));
        }
    }
    __syncthreads();

    // ---- layer 3: K=256 (16 ksteps), N=64; warp w -> cols w*8..w*8+7 ----
    {
        float c[4];
#pragma unroll
        for (int q = 0; q < 4; ++q) c[q] = 0.f;
        const u32 arow = arow_base + NOFF_A0;
        uint2 Bp = __ldg(&g_O3f[(w)*32 + l]);
#pragma unroll 4
        for (int t = 0; t < 16; ++t) {
            u32 a0, a1, a2, a3;
            ldmatrix_x4(a0, a1, a2, a3, arow + t * 32);
            uint2 Bn;
            if (t < 15) Bn = __ldg(&g_O3f[((t + 1) * 8 + w) * 32 + l]);
            hmma(c, a0, a1, a2, a3, Bp.x, Bp.y);
            Bp = Bn;
        }
        int col = w * 8 + cshift;
        float bb0 = __ldg(&o3b[col]), bb1 = __ldg(&o3b[col + 1]);
        *(float2*)&out[(row0 + ra) * 64 + col] = make_float2(c[0] + bb0, c[1] + bb1);
        *(float2*)&out[(row0 + ra + 8) * 64 + col] = make_float2(c[2] + bb0, c[3] + bb1);
    }
}

// ---------------- launch ----------------
extern "C" void kernel_launch(void* const* d_in, const int* in_sizes, int n_in,
                              void* d_out, int out_size) {
    const float* inputs = (const float*)d_in[0];
    const float* rel_types = (const float*)d_in[3];
    const float* W1 = (const float*)d_in[4];
    const float* b1 = (const float*)d_in[5];
    const float* W2 = (const float*)d_in[6];
    const float* b2 = (const float*)d_in[7];
    const float* O1 = (const float*)d_in[8];
    const float* o1b = (const float*)d_in[9];
    const float* O2 = (const float*)d_in[10];
    const float* o2b = (const float*)d_in[11];
    const float* O3 = (const float*)d_in[12];
    const float* o3b = (const float*)d_in[13];
    float* out = (float*)d_out;

    cudaFuncSetAttribute(edge_kernel, cudaFuncAttributeMaxDynamicSharedMemorySize, SMEM_EDGE);
    cudaFuncSetAttribute(node_kernel, cudaFuncAttributeMaxDynamicSharedMemorySize, SMEM_NODE);
    prep_kernel<<<160, 256>>>(W1, W2, O1, O2, O3);
    h1_kernel<<<BATCH * NNODE, 256>>>(inputs, b1);
    edge_kernel<<<BATCH * NNODE, 256, SMEM_EDGE>>>(rel_types, b2);
    node_kernel<<<256, 256, SMEM_NODE>>>(o1b, o2b, o3b, out);
}